// round 15
// baseline (speedup 1.0000x reference)
#include <cuda_runtime.h>
#include <cstdint>
#include <math.h>

// Problem constants
#define N_TOK 16384
#define DIM   2048
#define NE    8
#define KMAX  2048

// ---------------------------------------------------------------------------
// Scratch (__device__ globals; no runtime allocation allowed)
// ---------------------------------------------------------------------------
__device__ __align__(256) float g_xr [(size_t)N_TOK * DIM];   // tf32-rounded x
__device__ __align__(256) float g_wt [(size_t)DIM * DIM];     // W^T  (tf32)
__device__ __align__(256) float g_ukt[(size_t)KMAX * DIM];    // U_k^T (tf32, rows>=k zeroed)
__device__ __align__(256) float g_vr [(size_t)DIM * KMAX];    // V_k padded (tf32, cols>=k zeroed)
__device__ __align__(256) float g_xu [(size_t)N_TOK * KMAX];  // xu (fp32), then y (tf32) in place

// ---------------------------------------------------------------------------
// Helpers (sm_80-compatible only: cp.async + mma.sync tf32 + ldmatrix)
// ---------------------------------------------------------------------------
__device__ __forceinline__ uint32_t smem_u32(const void* p) {
    uint32_t a;
    asm("{ .reg .u64 t; cvta.to.shared.u64 t, %1; cvt.u32.u64 %0, t; }" : "=r"(a) : "l"(p));
    return a;
}
__device__ __forceinline__ float tf32r(float x) {
    uint32_t r; asm("cvt.rna.tf32.f32 %0, %1;" : "=r"(r) : "f"(x));
    return __uint_as_float(r);
}
__device__ __forceinline__ void cpa16(uint32_t s, const void* g) {
    asm volatile("cp.async.cg.shared.global [%0], [%1], 16;" :: "r"(s), "l"(g));
}
__device__ __forceinline__ void cpa_commit() {
    asm volatile("cp.async.commit_group;" ::: "memory");
}
template<int NN> __device__ __forceinline__ void cpa_wait() {
    asm volatile("cp.async.wait_group %0;" :: "n"(NN) : "memory");
}
__device__ __forceinline__ void mma_tf32(float c[4], const uint32_t a[4], const uint32_t b0, const uint32_t b1) {
    asm volatile(
        "mma.sync.aligned.m16n8k8.row.col.f32.tf32.tf32.f32 "
        "{%0,%1,%2,%3}, {%4,%5,%6,%7}, {%8,%9}, {%0,%1,%2,%3};"
        : "+f"(c[0]), "+f"(c[1]), "+f"(c[2]), "+f"(c[3])
        : "r"(a[0]), "r"(a[1]), "r"(a[2]), "r"(a[3]), "r"(b0), "r"(b1));
}
__device__ __forceinline__ void ldsm4(uint32_t r[4], uint32_t addr) {
    asm volatile("ldmatrix.sync.aligned.m8n8.x4.shared.b16 {%0,%1,%2,%3}, [%4];"
        : "=r"(r[0]), "=r"(r[1]), "=r"(r[2]), "=r"(r[3]) : "r"(addr));
}

// ---------------------------------------------------------------------------
// GEMM config: 128x128 CTA tile, 8 warps (2 M x 4 N), warp tile 64x32, BK=32,
// 3-stage cp.async pipeline. smem rows padded to 36 floats: row stride
// 144 B = 4 banks -> 8 rows x 16 B cover all 32 banks (ldmatrix conflict-free).
// ---------------------------------------------------------------------------
#define BM        128
#define BN        128
#define BK        32
#define ROWPAD    36
#define MAT_FLTS  (128 * ROWPAD)            // 4608 floats per matrix
#define STG_FLTS  (2 * MAT_FLTS)            // A + B = 9216 floats
#define NSTAGE    3
#define SMEM_FLTS (NSTAGE * STG_FLTS)       // 27648 floats = 110592 B
#define NTHR      256

// ---------------------------------------------------------------------------
// Unified tensor-core GEMM: out[128x128 tile] = A1@B1^T (steps1) [+ A2@B2^T]
// All matrices row-major, K-major, stride DIM floats. steps are BK-chunks.
// Epilogue multiplies by (1+v[col]) when vscale != nullptr.
// ---------------------------------------------------------------------------
__global__ __launch_bounds__(NTHR, 2) void gemm_tc(
    const float* __restrict__ A1, const float* __restrict__ B1, int steps1,
    const float* __restrict__ A2, const float* __restrict__ B2, int steps2,
    float* __restrict__ out, const float* __restrict__ vscale)
{
    extern __shared__ __align__(16) float sm[];
    uint32_t sb = smem_u32(sm);
    int tid = threadIdx.x;
    int wid = tid >> 5, lane = tid & 31;
    int lr = lane >> 2, lc = lane & 3;
    int nstart = blockIdx.y * BM;           // M offset (rows)
    int cstart = blockIdx.x * BN;           // N offset (cols)
    int total = steps1 + steps2;

    int m0w = (wid & 1) * 64;               // warp M origin in tile (0 or 64)
    int n0w = (wid >> 1) * 32;              // warp N origin in tile (0,32,64,96)

    // ldmatrix per-lane base offsets (bytes, within a stage's A / B matrix)
    int t8 = lane >> 3;                     // 8-lane group = tile index 0..3
    int r8 = lane & 7;                      // row within tile
    // A x4 tile order -> regs a0..a3: {rows+0,kl},{rows+8,kl},{rows+0,kh},{rows+8,kh}
    uint32_t loffA = (uint32_t)(((m0w + (t8 & 1) * 8 + r8) * ROWPAD + (t8 >> 1) * 4) * 4);
    // B x4 tile order -> regs: {n+0,kl},{n+0,kh},{n+8,kl},{n+8,kh} per 16-n group
    uint32_t loffB = (uint32_t)(((n0w + (t8 >> 1) * 8 + r8) * ROWPAD + (t8 & 1) * 4) * 4);

    float acc[4][4][4];                     // [m_atom][n_atom][reg] : 64x32 warp tile
    #pragma unroll
    for (int i = 0; i < 4; i++)
        #pragma unroll
        for (int j = 0; j < 4; j++)
            #pragma unroll
            for (int r = 0; r < 4; r++) acc[i][j][r] = 0.0f;

    // stage loader: iteration `it` -> stage (it % NSTAGE)
    auto load_it = [&](int it) {
        const float* Ab; const float* Bb; int off;
        if (it < steps1) { Ab = A1 + (size_t)nstart * DIM; Bb = B1 + (size_t)cstart * DIM; off = it * BK; }
        else             { Ab = A2 + (size_t)nstart * DIM; Bb = B2 + (size_t)cstart * DIM; off = (it - steps1) * BK; }
        int stage = it % NSTAGE;
        uint32_t sA = sb + (uint32_t)(stage * STG_FLTS) * 4u;
        uint32_t sB = sA + (uint32_t)MAT_FLTS * 4u;
        // per matrix: 128 rows x 8 16B-chunks = 1024 chunks; 256 threads -> 4 each
        #pragma unroll
        for (int l = 0; l < 4; l++) {
            int idx = tid + l * NTHR;
            int row = idx >> 3;
            int c4  = idx & 7;
            cpa16(sA + (uint32_t)(row * ROWPAD + c4 * 4) * 4u, Ab + (size_t)row * DIM + off + c4 * 4);
        }
        #pragma unroll
        for (int l = 0; l < 4; l++) {
            int idx = tid + l * NTHR;
            int row = idx >> 3;
            int c4  = idx & 7;
            cpa16(sB + (uint32_t)(row * ROWPAD + c4 * 4) * 4u, Bb + (size_t)row * DIM + off + c4 * 4);
        }
        cpa_commit();
    };

    // prologue: preload 2 stages (total >= 64 always)
    load_it(0);
    load_it(1);

    for (int it = 0; it < total; it++) {
        // committed = 2 + min(it, total-2); need group `it` done
        if (it == total - 1) cpa_wait<0>();
        else                 cpa_wait<1>();
        __syncthreads();

        // prefetch it+2 into stage (it-1)%3 (its consumer finished before the barrier)
        if (it + 2 < total) load_it(it + 2);

        uint32_t stA = sb + (uint32_t)((it % NSTAGE) * STG_FLTS) * 4u + loffA;
        uint32_t stB = sb + (uint32_t)((it % NSTAGE) * STG_FLTS + MAT_FLTS) * 4u + loffB;

        #pragma unroll
        for (int ks = 0; ks < BK / 8; ks++) {
            uint32_t kb = (uint32_t)(ks * 8 * 4);   // 8 floats per k-step
            uint32_t a[4][4], bp[2][4];
            #pragma unroll
            for (int im = 0; im < 4; im++)
                ldsm4(a[im], stA + (uint32_t)(im * 16 * ROWPAD * 4) + kb);
            #pragma unroll
            for (int p = 0; p < 2; p++)
                ldsm4(bp[p], stB + (uint32_t)(p * 16 * ROWPAD * 4) + kb);
            #pragma unroll
            for (int im = 0; im < 4; im++)
                #pragma unroll
                for (int jn = 0; jn < 4; jn++)
                    mma_tf32(acc[im][jn], a[im], bp[jn >> 1][(jn & 1) * 2], bp[jn >> 1][(jn & 1) * 2 + 1]);
        }
        __syncthreads();
    }

    // epilogue: c0,c1 -> (row, 2lc..2lc+1); c2,c3 -> (row+8, ...)
    #pragma unroll
    for (int im = 0; im < 4; im++) {
        int r0 = nstart + m0w + im * 16 + lr;
        #pragma unroll
        for (int jn = 0; jn < 4; jn++) {
            int col = cstart + n0w + jn * 8 + 2 * lc;
            float s0 = 1.0f, s1 = 1.0f;
            if (vscale) {
                s0 = 1.0f + vscale[col];
                s1 = 1.0f + vscale[col + 1];
            }
            float2 v0 = make_float2(acc[im][jn][0] * s0, acc[im][jn][1] * s1);
            float2 v1 = make_float2(acc[im][jn][2] * s0, acc[im][jn][3] * s1);
            *(float2*)(out + (size_t)r0 * DIM + col)       = v0;
            *(float2*)(out + (size_t)(r0 + 8) * DIM + col) = v1;
        }
    }
}

// ---------------------------------------------------------------------------
// Preprocessing kernels
// ---------------------------------------------------------------------------
__global__ void round_x(const float4* __restrict__ in, float4* __restrict__ outp, int n4) {
    for (int i = blockIdx.x * blockDim.x + threadIdx.x; i < n4; i += gridDim.x * blockDim.x) {
        float4 v = in[i];
        v.x = tf32r(v.x); v.y = tf32r(v.y); v.z = tf32r(v.z); v.w = tf32r(v.w);
        outp[i] = v;
    }
}

__global__ void trans_w(const float* __restrict__ W) {
    __shared__ float tile[32][33];
    int c0 = blockIdx.x * 32, d0 = blockIdx.y * 32;
    int tx = threadIdx.x;
    for (int i = threadIdx.y; i < 32; i += 8)
        tile[i][tx] = tf32r(W[(size_t)(d0 + i) * DIM + c0 + tx]);
    __syncthreads();
    for (int i = threadIdx.y; i < 32; i += 8)
        g_wt[(size_t)(c0 + i) * DIM + d0 + tx] = tile[tx][i];
}

__global__ void trans_u(const float* __restrict__ Uk, int k) {
    __shared__ float tile[32][33];
    int c0 = blockIdx.x * 32, d0 = blockIdx.y * 32;
    int tx = threadIdx.x;
    for (int i = threadIdx.y; i < 32; i += 8) {
        int c = c0 + tx;
        tile[i][tx] = (c < k) ? tf32r(Uk[(size_t)(d0 + i) * k + c]) : 0.0f;
    }
    __syncthreads();
    for (int i = threadIdx.y; i < 32; i += 8)
        g_ukt[(size_t)(c0 + i) * DIM + d0 + tx] = tile[tx][i];
}

__global__ void pad_v(const float* __restrict__ Vk, int k, int KP) {
    int total = DIM * KP;
    for (int idx = blockIdx.x * blockDim.x + threadIdx.x; idx < total; idx += gridDim.x * blockDim.x) {
        int d = idx / KP;
        int c = idx - d * KP;
        g_vr[(size_t)d * DIM + c] = (c < k) ? tf32r(Vk[(size_t)d * k + c]) : 0.0f;
    }
}

// ---------------------------------------------------------------------------
// Routing: s = xu.Wg1; g = softmax(s*Wg2); coef = g@lam; y = tf32(xu*coef)
// xu rows are DIM-strided (written by gemm_tc epilogue).
// ---------------------------------------------------------------------------
__global__ __launch_bounds__(256) void route_scale(
    const float* __restrict__ Wg1, const float* __restrict__ Wg2,
    const float* __restrict__ lam, int k, int KP)
{
    int n = blockIdx.x;
    float* row = g_xu + (size_t)n * DIM;
    __shared__ float red[256];
    int tid = threadIdx.x;

    float p = 0.0f;
    for (int c = tid; c < k; c += 256) p += row[c] * Wg1[c];
    red[tid] = p;
    __syncthreads();
    #pragma unroll
    for (int s = 128; s > 0; s >>= 1) {
        if (tid < s) red[tid] += red[tid + s];
        __syncthreads();
    }
    float sv = red[0];

    float g[NE];
    float m = -1e30f;
    #pragma unroll
    for (int e = 0; e < NE; e++) { g[e] = sv * Wg2[e]; m = fmaxf(m, g[e]); }
    float sum = 0.0f;
    #pragma unroll
    for (int e = 0; e < NE; e++) { g[e] = expf(g[e] - m); sum += g[e]; }
    float inv = 1.0f / sum;
    #pragma unroll
    for (int e = 0; e < NE; e++) g[e] *= inv;

    for (int c = tid; c < KP; c += 256) {
        float coef = 0.0f;
        if (c < k) {
            #pragma unroll
            for (int e = 0; e < NE; e++) coef += g[e] * lam[(size_t)e * k + c];
        }
        row[c] = tf32r(row[c] * coef);
    }
}

// ---------------------------------------------------------------------------
// Launch  (order chosen so launch index 3 = gemm_xu for ncu capture)
// ---------------------------------------------------------------------------
extern "C" void kernel_launch(void* const* d_in, const int* in_sizes, int n_in,
                              void* d_out, int out_size)
{
    const float* x   = (const float*)d_in[0];  // [N, D]
    const float* W   = (const float*)d_in[1];  // [D, D]
    const float* Uk  = (const float*)d_in[2];  // [D, k]
    const float* Vk  = (const float*)d_in[3];  // [D, k]
    const float* lam = (const float*)d_in[4];  // [E, k]
    const float* v   = (const float*)d_in[5];  // [D]
    const float* Wg1 = (const float*)d_in[6];  // [k, 1]
    const float* Wg2 = (const float*)d_in[7];  // [1, E]
    float* out = (float*)d_out;

    int k = in_sizes[2] / DIM;
    if (k > KMAX) k = KMAX;
    int KP = ((k + 127) / 128) * 128;
    if (KP > KMAX) KP = KMAX;

    size_t smem_bytes = SMEM_FLTS * sizeof(float);  // 110592
    cudaFuncSetAttribute(gemm_tc, cudaFuncAttributeMaxDynamicSharedMemorySize, (int)smem_bytes);

    float* xr;  cudaGetSymbolAddress((void**)&xr,  g_xr);
    float* ukt; cudaGetSymbolAddress((void**)&ukt, g_ukt);
    float* vr;  cudaGetSymbolAddress((void**)&vr,  g_vr);
    float* xu;  cudaGetSymbolAddress((void**)&xu,  g_xu);
    float* wt;  cudaGetSymbolAddress((void**)&wt,  g_wt);

    // 1) operand prep needed by gemm_xu
    round_x<<<4096, 256>>>((const float4*)x, (float4*)xr, N_TOK * DIM / 4);
    trans_w<<<dim3(DIM / 32, DIM / 32), dim3(32, 8)>>>(W);
    trans_u<<<dim3(KP / 32, DIM / 32), dim3(32, 8)>>>(Uk, k);

    // 2) xu = x @ U_k   (launch index 3 -> ncu capture slot)
    gemm_tc<<<dim3(KP / BN, N_TOK / BM), NTHR, smem_bytes>>>(
        xr, ukt, DIM / BK, nullptr, nullptr, 0, xu, nullptr);

    // 3) remaining prep for gemm_out (independent of gemm_xu)
    pad_v<<<4096, 256>>>(Vk, k, KP);

    // 4) routing + in-place y = tf32(xu * coef)
    route_scale<<<N_TOK, 256>>>(Wg1, Wg2, lam, k, KP);

    // 5) out = (x@W + y@V^T) * (1+v)   (fused K, tensor cores)
    gemm_tc<<<dim3(DIM / BN, N_TOK / BM), NTHR, smem_bytes>>>(
        xr, wt, DIM / BK, xu, vr, KP / BK, out, v);
}

// round 16
// speedup vs baseline: 1.1236x; 1.1236x over previous
#include <cuda_runtime.h>
#include <cstdint>
#include <math.h>

// Problem constants
#define N_TOK 16384
#define DIM   2048
#define NE    8
#define KMAX  2048

// ---------------------------------------------------------------------------
// Scratch (__device__ globals; no runtime allocation allowed)
// ---------------------------------------------------------------------------
__device__ __align__(256) float g_xr [(size_t)N_TOK * DIM];   // tf32-rounded x
__device__ __align__(256) float g_wt [(size_t)DIM * DIM];     // W^T  (tf32)
__device__ __align__(256) float g_ukt[(size_t)KMAX * DIM];    // U_k^T (tf32, rows>=k zeroed)
__device__ __align__(256) float g_vr [(size_t)DIM * KMAX];    // V_k padded (tf32, cols>=k zeroed)
__device__ __align__(256) float g_xu [(size_t)N_TOK * KMAX];  // xu (fp32), then y (tf32) in place

// ---------------------------------------------------------------------------
// Helpers (sm_80-compatible only: cp.async + mma.sync tf32 + ldmatrix)
// ---------------------------------------------------------------------------
__device__ __forceinline__ uint32_t smem_u32(const void* p) {
    uint32_t a;
    asm("{ .reg .u64 t; cvta.to.shared.u64 t, %1; cvt.u32.u64 %0, t; }" : "=r"(a) : "l"(p));
    return a;
}
__device__ __forceinline__ float tf32r(float x) {
    uint32_t r; asm("cvt.rna.tf32.f32 %0, %1;" : "=r"(r) : "f"(x));
    return __uint_as_float(r);
}
__device__ __forceinline__ void cpa16(uint32_t s, const void* g) {
    asm volatile("cp.async.cg.shared.global [%0], [%1], 16;" :: "r"(s), "l"(g));
}
__device__ __forceinline__ void cpa_commit() {
    asm volatile("cp.async.commit_group;" ::: "memory");
}
template<int NN> __device__ __forceinline__ void cpa_wait() {
    asm volatile("cp.async.wait_group %0;" :: "n"(NN) : "memory");
}
__device__ __forceinline__ void mma_tf32(float c[4], const uint32_t a[4], const uint32_t b0, const uint32_t b1) {
    asm volatile(
        "mma.sync.aligned.m16n8k8.row.col.f32.tf32.tf32.f32 "
        "{%0,%1,%2,%3}, {%4,%5,%6,%7}, {%8,%9}, {%0,%1,%2,%3};"
        : "+f"(c[0]), "+f"(c[1]), "+f"(c[2]), "+f"(c[3])
        : "r"(a[0]), "r"(a[1]), "r"(a[2]), "r"(a[3]), "r"(b0), "r"(b1));
}
__device__ __forceinline__ void ldsm4(uint32_t r[4], uint32_t addr) {
    asm volatile("ldmatrix.sync.aligned.m8n8.x4.shared.b16 {%0,%1,%2,%3}, [%4];"
        : "=r"(r[0]), "=r"(r[1]), "=r"(r[2]), "=r"(r[3]) : "r"(addr));
}

// ---------------------------------------------------------------------------
// GEMM config: 128x128 CTA tile, 4 warps (2x2), warp tile 64x64, BK=32,
// 3-stage cp.async pipeline. smem rows padded to 36 floats: row stride
// 144 B = 4 banks -> 8 rows x 16 B cover all 32 banks (ldmatrix conflict-free).
// ---------------------------------------------------------------------------
#define BM        128
#define BN        128
#define BK        32
#define ROWPAD    36
#define MAT_FLTS  (128 * ROWPAD)            // 4608 floats per matrix
#define STG_FLTS  (2 * MAT_FLTS)            // A + B = 9216 floats
#define NSTAGE    3
#define SMEM_FLTS (NSTAGE * STG_FLTS)       // 27648 floats = 110592 B
#define NTHR      128

// ---------------------------------------------------------------------------
// Unified tensor-core GEMM: out[128x128 tile] = A1@B1^T (steps1) [+ A2@B2^T]
// All matrices row-major, K-major, stride DIM floats. steps are BK-chunks.
// Epilogue multiplies by (1+v[col]) when vscale != nullptr.
// ks-loop fragments are double-buffered (software pipeline over ldmatrix).
// ---------------------------------------------------------------------------
__global__ __launch_bounds__(NTHR, 2) void gemm_tc(
    const float* __restrict__ A1, const float* __restrict__ B1, int steps1,
    const float* __restrict__ A2, const float* __restrict__ B2, int steps2,
    float* __restrict__ out, const float* __restrict__ vscale)
{
    extern __shared__ __align__(16) float sm[];
    uint32_t sb = smem_u32(sm);
    int tid = threadIdx.x;
    int wid = tid >> 5, lane = tid & 31;
    int lr = lane >> 2, lc = lane & 3;
    int nstart = blockIdx.y * BM;           // M offset (rows)
    int cstart = blockIdx.x * BN;           // N offset (cols)
    int total = steps1 + steps2;

    int m0w = (wid & 1) * 64;               // warp M origin in tile
    int n0w = (wid >> 1) * 64;              // warp N origin in tile

    // ldmatrix per-lane base offsets (bytes, within a stage's A / B matrix)
    int t8 = lane >> 3;                     // 8-lane group = tile index 0..3
    int r8 = lane & 7;                      // row within tile
    // A x4 tile order -> regs a0..a3: {rows+0,kl},{rows+8,kl},{rows+0,kh},{rows+8,kh}
    uint32_t loffA = (uint32_t)(((m0w + (t8 & 1) * 8 + r8) * ROWPAD + (t8 >> 1) * 4) * 4);
    // B x4 tile order -> b[2p][0], b[2p][1], b[2p+1][0], b[2p+1][1]
    uint32_t loffB = (uint32_t)(((n0w + (t8 >> 1) * 8 + r8) * ROWPAD + (t8 & 1) * 4) * 4);

    float acc[4][8][4];                     // [m_atom][n_atom][reg] : 64x64 warp tile
    #pragma unroll
    for (int i = 0; i < 4; i++)
        #pragma unroll
        for (int j = 0; j < 8; j++)
            #pragma unroll
            for (int r = 0; r < 4; r++) acc[i][j][r] = 0.0f;

    // stage loader: iteration `it` -> stage (it % NSTAGE)
    auto load_it = [&](int it) {
        const float* Ab; const float* Bb; int off;
        if (it < steps1) { Ab = A1 + (size_t)nstart * DIM; Bb = B1 + (size_t)cstart * DIM; off = it * BK; }
        else             { Ab = A2 + (size_t)nstart * DIM; Bb = B2 + (size_t)cstart * DIM; off = (it - steps1) * BK; }
        int stage = it % NSTAGE;
        uint32_t sA = sb + (uint32_t)(stage * STG_FLTS) * 4u;
        uint32_t sB = sA + (uint32_t)MAT_FLTS * 4u;
        // per matrix: 128 rows x 8 16B-chunks = 1024 chunks; 128 threads -> 8 each
        #pragma unroll
        for (int l = 0; l < 8; l++) {
            int idx = tid + l * NTHR;
            int row = idx >> 3;
            int c4  = idx & 7;
            cpa16(sA + (uint32_t)(row * ROWPAD + c4 * 4) * 4u, Ab + (size_t)row * DIM + off + c4 * 4);
        }
        #pragma unroll
        for (int l = 0; l < 8; l++) {
            int idx = tid + l * NTHR;
            int row = idx >> 3;
            int c4  = idx & 7;
            cpa16(sB + (uint32_t)(row * ROWPAD + c4 * 4) * 4u, Bb + (size_t)row * DIM + off + c4 * 4);
        }
        cpa_commit();
    };

    // prologue: preload 2 stages (total >= 64 always)
    load_it(0);
    load_it(1);

    for (int it = 0; it < total; it++) {
        // committed = 2 + min(it, total-2); need group `it` done
        if (it == total - 1) cpa_wait<0>();
        else                 cpa_wait<1>();
        __syncthreads();

        // prefetch it+2 into stage (it-1)%3 (its consumer finished before the barrier)
        if (it + 2 < total) load_it(it + 2);

        uint32_t stA = sb + (uint32_t)((it % NSTAGE) * STG_FLTS) * 4u + loffA;
        uint32_t stB = sb + (uint32_t)((it % NSTAGE) * STG_FLTS + MAT_FLTS) * 4u + loffB;

        // double-buffered fragments: ldsm for ks+1 issue before MMAs of ks
        uint32_t afr[2][4][4], bfr[2][4][4];
        #pragma unroll
        for (int im = 0; im < 4; im++)
            ldsm4(afr[0][im], stA + (uint32_t)(im * 16 * ROWPAD * 4));
        #pragma unroll
        for (int p = 0; p < 4; p++)
            ldsm4(bfr[0][p], stB + (uint32_t)(p * 16 * ROWPAD * 4));

        #pragma unroll
        for (int ks = 0; ks < BK / 8; ks++) {
            int cur = ks & 1, nxt = cur ^ 1;
            if (ks < BK / 8 - 1) {
                uint32_t kb = (uint32_t)((ks + 1) * 8 * 4);
                #pragma unroll
                for (int im = 0; im < 4; im++)
                    ldsm4(afr[nxt][im], stA + (uint32_t)(im * 16 * ROWPAD * 4) + kb);
                #pragma unroll
                for (int p = 0; p < 4; p++)
                    ldsm4(bfr[nxt][p], stB + (uint32_t)(p * 16 * ROWPAD * 4) + kb);
            }
            #pragma unroll
            for (int im = 0; im < 4; im++)
                #pragma unroll
                for (int jn = 0; jn < 8; jn++)
                    mma_tf32(acc[im][jn], afr[cur][im],
                             bfr[cur][jn >> 1][(jn & 1) * 2],
                             bfr[cur][jn >> 1][(jn & 1) * 2 + 1]);
        }
        __syncthreads();
    }

    // epilogue: c0,c1 -> (row, 2lc..2lc+1); c2,c3 -> (row+8, ...)
    #pragma unroll
    for (int im = 0; im < 4; im++) {
        int r0 = nstart + m0w + im * 16 + lr;
        #pragma unroll
        for (int jn = 0; jn < 8; jn++) {
            int col = cstart + n0w + jn * 8 + 2 * lc;
            float s0 = 1.0f, s1 = 1.0f;
            if (vscale) {
                s0 = 1.0f + vscale[col];
                s1 = 1.0f + vscale[col + 1];
            }
            float2 v0 = make_float2(acc[im][jn][0] * s0, acc[im][jn][1] * s1);
            float2 v1 = make_float2(acc[im][jn][2] * s0, acc[im][jn][3] * s1);
            *(float2*)(out + (size_t)r0 * DIM + col)       = v0;
            *(float2*)(out + (size_t)(r0 + 8) * DIM + col) = v1;
        }
    }
}

// ---------------------------------------------------------------------------
// Preprocessing kernels
// ---------------------------------------------------------------------------
__global__ void round_x(const float4* __restrict__ in, float4* __restrict__ outp, int n4) {
    for (int i = blockIdx.x * blockDim.x + threadIdx.x; i < n4; i += gridDim.x * blockDim.x) {
        float4 v = in[i];
        v.x = tf32r(v.x); v.y = tf32r(v.y); v.z = tf32r(v.z); v.w = tf32r(v.w);
        outp[i] = v;
    }
}

__global__ void trans_w(const float* __restrict__ W) {
    __shared__ float tile[32][33];
    int c0 = blockIdx.x * 32, d0 = blockIdx.y * 32;
    int tx = threadIdx.x;
    for (int i = threadIdx.y; i < 32; i += 8)
        tile[i][tx] = tf32r(W[(size_t)(d0 + i) * DIM + c0 + tx]);
    __syncthreads();
    for (int i = threadIdx.y; i < 32; i += 8)
        g_wt[(size_t)(c0 + i) * DIM + d0 + tx] = tile[tx][i];
}

__global__ void trans_u(const float* __restrict__ Uk, int k) {
    __shared__ float tile[32][33];
    int c0 = blockIdx.x * 32, d0 = blockIdx.y * 32;
    int tx = threadIdx.x;
    for (int i = threadIdx.y; i < 32; i += 8) {
        int c = c0 + tx;
        tile[i][tx] = (c < k) ? tf32r(Uk[(size_t)(d0 + i) * k + c]) : 0.0f;
    }
    __syncthreads();
    for (int i = threadIdx.y; i < 32; i += 8)
        g_ukt[(size_t)(c0 + i) * DIM + d0 + tx] = tile[tx][i];
}

__global__ void pad_v(const float* __restrict__ Vk, int k, int KP) {
    int total = DIM * KP;
    for (int idx = blockIdx.x * blockDim.x + threadIdx.x; idx < total; idx += gridDim.x * blockDim.x) {
        int d = idx / KP;
        int c = idx - d * KP;
        g_vr[(size_t)d * DIM + c] = (c < k) ? tf32r(Vk[(size_t)d * k + c]) : 0.0f;
    }
}

// ---------------------------------------------------------------------------
// Routing: s = xu.Wg1; g = softmax(s*Wg2); coef = g@lam; y = tf32(xu*coef)
// xu rows are DIM-strided (written by gemm_tc epilogue).
// ---------------------------------------------------------------------------
__global__ __launch_bounds__(256) void route_scale(
    const float* __restrict__ Wg1, const float* __restrict__ Wg2,
    const float* __restrict__ lam, int k, int KP)
{
    int n = blockIdx.x;
    float* row = g_xu + (size_t)n * DIM;
    __shared__ float red[256];
    int tid = threadIdx.x;

    float p = 0.0f;
    for (int c = tid; c < k; c += 256) p += row[c] * Wg1[c];
    red[tid] = p;
    __syncthreads();
    #pragma unroll
    for (int s = 128; s > 0; s >>= 1) {
        if (tid < s) red[tid] += red[tid + s];
        __syncthreads();
    }
    float sv = red[0];

    float g[NE];
    float m = -1e30f;
    #pragma unroll
    for (int e = 0; e < NE; e++) { g[e] = sv * Wg2[e]; m = fmaxf(m, g[e]); }
    float sum = 0.0f;
    #pragma unroll
    for (int e = 0; e < NE; e++) { g[e] = expf(g[e] - m); sum += g[e]; }
    float inv = 1.0f / sum;
    #pragma unroll
    for (int e = 0; e < NE; e++) g[e] *= inv;

    for (int c = tid; c < KP; c += 256) {
        float coef = 0.0f;
        if (c < k) {
            #pragma unroll
            for (int e = 0; e < NE; e++) coef += g[e] * lam[(size_t)e * k + c];
        }
        row[c] = tf32r(row[c] * coef);
    }
}

// ---------------------------------------------------------------------------
// Launch  (order chosen so launch index 3 = gemm_xu for ncu capture)
// ---------------------------------------------------------------------------
extern "C" void kernel_launch(void* const* d_in, const int* in_sizes, int n_in,
                              void* d_out, int out_size)
{
    const float* x   = (const float*)d_in[0];  // [N, D]
    const float* W   = (const float*)d_in[1];  // [D, D]
    const float* Uk  = (const float*)d_in[2];  // [D, k]
    const float* Vk  = (const float*)d_in[3];  // [D, k]
    const float* lam = (const float*)d_in[4];  // [E, k]
    const float* v   = (const float*)d_in[5];  // [D]
    const float* Wg1 = (const float*)d_in[6];  // [k, 1]
    const float* Wg2 = (const float*)d_in[7];  // [1, E]
    float* out = (float*)d_out;

    int k = in_sizes[2] / DIM;
    if (k > KMAX) k = KMAX;
    int KP = ((k + 127) / 128) * 128;
    if (KP > KMAX) KP = KMAX;

    size_t smem_bytes = SMEM_FLTS * sizeof(float);  // 110592
    cudaFuncSetAttribute(gemm_tc, cudaFuncAttributeMaxDynamicSharedMemorySize, (int)smem_bytes);

    float* xr;  cudaGetSymbolAddress((void**)&xr,  g_xr);
    float* ukt; cudaGetSymbolAddress((void**)&ukt, g_ukt);
    float* vr;  cudaGetSymbolAddress((void**)&vr,  g_vr);
    float* xu;  cudaGetSymbolAddress((void**)&xu,  g_xu);
    float* wt;  cudaGetSymbolAddress((void**)&wt,  g_wt);

    // 1) operand prep needed by gemm_xu
    round_x<<<4096, 256>>>((const float4*)x, (float4*)xr, N_TOK * DIM / 4);
    trans_w<<<dim3(DIM / 32, DIM / 32), dim3(32, 8)>>>(W);
    trans_u<<<dim3(KP / 32, DIM / 32), dim3(32, 8)>>>(Uk, k);

    // 2) xu = x @ U_k   (launch index 3 -> ncu capture slot)
    gemm_tc<<<dim3(KP / BN, N_TOK / BM), NTHR, smem_bytes>>>(
        xr, ukt, DIM / BK, nullptr, nullptr, 0, xu, nullptr);

    // 3) remaining prep for gemm_out (independent of gemm_xu)
    pad_v<<<4096, 256>>>(Vk, k, KP);

    // 4) routing + in-place y = tf32(xu * coef)
    route_scale<<<N_TOK, 256>>>(Wg1, Wg2, lam, k, KP);

    // 5) out = (x@W + y@V^T) * (1+v)   (fused K, tensor cores)
    gemm_tc<<<dim3(DIM / BN, N_TOK / BM), NTHR, smem_bytes>>>(
        xr, wt, DIM / BK, xu, vr, KP / BK, out, v);
}

// round 17
// speedup vs baseline: 1.1608x; 1.0331x over previous
#include <cuda_runtime.h>
#include <cstdint>
#include <math.h>

// Problem constants
#define N_TOK 16384
#define DIM   2048
#define NE    8
#define KMAX  2048

// ---------------------------------------------------------------------------
// Scratch (__device__ globals; no runtime allocation allowed)
// Note: x is fed RAW to the tf32 MMAs (HW truncates low mantissa bits);
// only the B operands (W^T, U^T, V) are RNA-rounded during transpose/pad.
// ---------------------------------------------------------------------------
__device__ __align__(256) float g_wt [(size_t)DIM * DIM];     // W^T  (tf32 RNA)
__device__ __align__(256) float g_ukt[(size_t)KMAX * DIM];    // U_k^T (tf32 RNA, rows>=k zeroed)
__device__ __align__(256) float g_vr [(size_t)DIM * KMAX];    // V_k padded (tf32 RNA, cols>=k zeroed)
__device__ __align__(256) float g_xu [(size_t)N_TOK * KMAX];  // xu (fp32), then y (tf32) in place

// ---------------------------------------------------------------------------
// Helpers (sm_80-compatible only: cp.async + mma.sync tf32 + ldmatrix)
// ---------------------------------------------------------------------------
__device__ __forceinline__ uint32_t smem_u32(const void* p) {
    uint32_t a;
    asm("{ .reg .u64 t; cvta.to.shared.u64 t, %1; cvt.u32.u64 %0, t; }" : "=r"(a) : "l"(p));
    return a;
}
__device__ __forceinline__ float tf32r(float x) {
    uint32_t r; asm("cvt.rna.tf32.f32 %0, %1;" : "=r"(r) : "f"(x));
    return __uint_as_float(r);
}
__device__ __forceinline__ void cpa16(uint32_t s, const void* g) {
    asm volatile("cp.async.cg.shared.global [%0], [%1], 16;" :: "r"(s), "l"(g));
}
__device__ __forceinline__ void cpa_commit() {
    asm volatile("cp.async.commit_group;" ::: "memory");
}
template<int NN> __device__ __forceinline__ void cpa_wait() {
    asm volatile("cp.async.wait_group %0;" :: "n"(NN) : "memory");
}
__device__ __forceinline__ void mma_tf32(float c[4], const uint32_t a[4], const uint32_t b0, const uint32_t b1) {
    asm volatile(
        "mma.sync.aligned.m16n8k8.row.col.f32.tf32.tf32.f32 "
        "{%0,%1,%2,%3}, {%4,%5,%6,%7}, {%8,%9}, {%0,%1,%2,%3};"
        : "+f"(c[0]), "+f"(c[1]), "+f"(c[2]), "+f"(c[3])
        : "r"(a[0]), "r"(a[1]), "r"(a[2]), "r"(a[3]), "r"(b0), "r"(b1));
}
__device__ __forceinline__ void ldsm4(uint32_t r[4], uint32_t addr) {
    asm volatile("ldmatrix.sync.aligned.m8n8.x4.shared.b16 {%0,%1,%2,%3}, [%4];"
        : "=r"(r[0]), "=r"(r[1]), "=r"(r[2]), "=r"(r[3]) : "r"(addr));
}

// ---------------------------------------------------------------------------
// GEMM config: 128x128 CTA tile, 4 warps (2x2), warp tile 64x64, BK=32,
// 3-stage cp.async pipeline. smem rows padded to 36 floats: row stride
// 144 B = 4 banks -> 8 rows x 16 B cover all 32 banks (ldmatrix conflict-free).
// ---------------------------------------------------------------------------
#define BM        128
#define BN        128
#define BK        32
#define ROWPAD    36
#define MAT_FLTS  (128 * ROWPAD)            // 4608 floats per matrix
#define STG_FLTS  (2 * MAT_FLTS)            // A + B = 9216 floats
#define NSTAGE    3
#define SMEM_FLTS (NSTAGE * STG_FLTS)       // 27648 floats = 110592 B
#define NTHR      128

// ---------------------------------------------------------------------------
// Unified tensor-core GEMM: out[128x128 tile] = A1@B1^T (steps1) [+ A2@B2^T]
// All matrices row-major, K-major, stride DIM floats. steps are BK-chunks.
// Epilogue multiplies by (1+v[col]) when vscale != nullptr.
// ks-loop fragments are double-buffered (software pipeline over ldmatrix).
// ---------------------------------------------------------------------------
__global__ __launch_bounds__(NTHR, 2) void gemm_tc(
    const float* __restrict__ A1, const float* __restrict__ B1, int steps1,
    const float* __restrict__ A2, const float* __restrict__ B2, int steps2,
    float* __restrict__ out, const float* __restrict__ vscale)
{
    extern __shared__ __align__(16) float sm[];
    uint32_t sb = smem_u32(sm);
    int tid = threadIdx.x;
    int wid = tid >> 5, lane = tid & 31;
    int lr = lane >> 2, lc = lane & 3;
    int nstart = blockIdx.y * BM;           // M offset (rows)
    int cstart = blockIdx.x * BN;           // N offset (cols)
    int total = steps1 + steps2;

    int m0w = (wid & 1) * 64;               // warp M origin in tile
    int n0w = (wid >> 1) * 64;              // warp N origin in tile

    // ldmatrix per-lane base offsets (bytes, within a stage's A / B matrix)
    int t8 = lane >> 3;                     // 8-lane group = tile index 0..3
    int r8 = lane & 7;                      // row within tile
    // A x4 tile order -> regs a0..a3: {rows+0,kl},{rows+8,kl},{rows+0,kh},{rows+8,kh}
    uint32_t loffA = (uint32_t)(((m0w + (t8 & 1) * 8 + r8) * ROWPAD + (t8 >> 1) * 4) * 4);
    // B x4 tile order -> b[2p][0], b[2p][1], b[2p+1][0], b[2p+1][1]
    uint32_t loffB = (uint32_t)(((n0w + (t8 >> 1) * 8 + r8) * ROWPAD + (t8 & 1) * 4) * 4);

    float acc[4][8][4];                     // [m_atom][n_atom][reg] : 64x64 warp tile
    #pragma unroll
    for (int i = 0; i < 4; i++)
        #pragma unroll
        for (int j = 0; j < 8; j++)
            #pragma unroll
            for (int r = 0; r < 4; r++) acc[i][j][r] = 0.0f;

    // stage loader: iteration `it` -> stage (it % NSTAGE)
    auto load_it = [&](int it) {
        const float* Ab; const float* Bb; int off;
        if (it < steps1) { Ab = A1 + (size_t)nstart * DIM; Bb = B1 + (size_t)cstart * DIM; off = it * BK; }
        else             { Ab = A2 + (size_t)nstart * DIM; Bb = B2 + (size_t)cstart * DIM; off = (it - steps1) * BK; }
        int stage = it % NSTAGE;
        uint32_t sA = sb + (uint32_t)(stage * STG_FLTS) * 4u;
        uint32_t sB = sA + (uint32_t)MAT_FLTS * 4u;
        // per matrix: 128 rows x 8 16B-chunks = 1024 chunks; 128 threads -> 8 each
        #pragma unroll
        for (int l = 0; l < 8; l++) {
            int idx = tid + l * NTHR;
            int row = idx >> 3;
            int c4  = idx & 7;
            cpa16(sA + (uint32_t)(row * ROWPAD + c4 * 4) * 4u, Ab + (size_t)row * DIM + off + c4 * 4);
        }
        #pragma unroll
        for (int l = 0; l < 8; l++) {
            int idx = tid + l * NTHR;
            int row = idx >> 3;
            int c4  = idx & 7;
            cpa16(sB + (uint32_t)(row * ROWPAD + c4 * 4) * 4u, Bb + (size_t)row * DIM + off + c4 * 4);
        }
        cpa_commit();
    };

    // prologue: preload 2 stages (total >= 64 always)
    load_it(0);
    load_it(1);

    for (int it = 0; it < total; it++) {
        // committed = 2 + min(it, total-2); need group `it` done
        if (it == total - 1) cpa_wait<0>();
        else                 cpa_wait<1>();
        __syncthreads();

        // prefetch it+2 into stage (it-1)%3 (its consumer finished before the barrier)
        if (it + 2 < total) load_it(it + 2);

        uint32_t stA = sb + (uint32_t)((it % NSTAGE) * STG_FLTS) * 4u + loffA;
        uint32_t stB = sb + (uint32_t)((it % NSTAGE) * STG_FLTS + MAT_FLTS) * 4u + loffB;

        // double-buffered fragments: ldsm for ks+1 issue before MMAs of ks
        uint32_t afr[2][4][4], bfr[2][4][4];
        #pragma unroll
        for (int im = 0; im < 4; im++)
            ldsm4(afr[0][im], stA + (uint32_t)(im * 16 * ROWPAD * 4));
        #pragma unroll
        for (int p = 0; p < 4; p++)
            ldsm4(bfr[0][p], stB + (uint32_t)(p * 16 * ROWPAD * 4));

        #pragma unroll
        for (int ks = 0; ks < BK / 8; ks++) {
            int cur = ks & 1, nxt = cur ^ 1;
            if (ks < BK / 8 - 1) {
                uint32_t kb = (uint32_t)((ks + 1) * 8 * 4);
                #pragma unroll
                for (int im = 0; im < 4; im++)
                    ldsm4(afr[nxt][im], stA + (uint32_t)(im * 16 * ROWPAD * 4) + kb);
                #pragma unroll
                for (int p = 0; p < 4; p++)
                    ldsm4(bfr[nxt][p], stB + (uint32_t)(p * 16 * ROWPAD * 4) + kb);
            }
            #pragma unroll
            for (int im = 0; im < 4; im++)
                #pragma unroll
                for (int jn = 0; jn < 8; jn++)
                    mma_tf32(acc[im][jn], afr[cur][im],
                             bfr[cur][jn >> 1][(jn & 1) * 2],
                             bfr[cur][jn >> 1][(jn & 1) * 2 + 1]);
        }
        __syncthreads();
    }

    // epilogue: c0,c1 -> (row, 2lc..2lc+1); c2,c3 -> (row+8, ...)
    #pragma unroll
    for (int im = 0; im < 4; im++) {
        int r0 = nstart + m0w + im * 16 + lr;
        #pragma unroll
        for (int jn = 0; jn < 8; jn++) {
            int col = cstart + n0w + jn * 8 + 2 * lc;
            float s0 = 1.0f, s1 = 1.0f;
            if (vscale) {
                s0 = 1.0f + vscale[col];
                s1 = 1.0f + vscale[col + 1];
            }
            float2 v0 = make_float2(acc[im][jn][0] * s0, acc[im][jn][1] * s1);
            float2 v1 = make_float2(acc[im][jn][2] * s0, acc[im][jn][3] * s1);
            *(float2*)(out + (size_t)r0 * DIM + col)       = v0;
            *(float2*)(out + (size_t)(r0 + 8) * DIM + col) = v1;
        }
    }
}

// ---------------------------------------------------------------------------
// Preprocessing kernels (B operands only; A = raw x, truncated by MMA HW)
// ---------------------------------------------------------------------------
__global__ void trans_w(const float* __restrict__ W) {
    __shared__ float tile[32][33];
    int c0 = blockIdx.x * 32, d0 = blockIdx.y * 32;
    int tx = threadIdx.x;
    for (int i = threadIdx.y; i < 32; i += 8)
        tile[i][tx] = tf32r(W[(size_t)(d0 + i) * DIM + c0 + tx]);
    __syncthreads();
    for (int i = threadIdx.y; i < 32; i += 8)
        g_wt[(size_t)(c0 + i) * DIM + d0 + tx] = tile[tx][i];
}

__global__ void trans_u(const float* __restrict__ Uk, int k) {
    __shared__ float tile[32][33];
    int c0 = blockIdx.x * 32, d0 = blockIdx.y * 32;
    int tx = threadIdx.x;
    for (int i = threadIdx.y; i < 32; i += 8) {
        int c = c0 + tx;
        tile[i][tx] = (c < k) ? tf32r(Uk[(size_t)(d0 + i) * k + c]) : 0.0f;
    }
    __syncthreads();
    for (int i = threadIdx.y; i < 32; i += 8)
        g_ukt[(size_t)(c0 + i) * DIM + d0 + tx] = tile[tx][i];
}

__global__ void pad_v(const float* __restrict__ Vk, int k, int KP) {
    int total = DIM * KP;
    for (int idx = blockIdx.x * blockDim.x + threadIdx.x; idx < total; idx += gridDim.x * blockDim.x) {
        int d = idx / KP;
        int c = idx - d * KP;
        g_vr[(size_t)d * DIM + c] = (c < k) ? tf32r(Vk[(size_t)d * k + c]) : 0.0f;
    }
}

// ---------------------------------------------------------------------------
// Routing: s = xu.Wg1; g = softmax(s*Wg2); coef = g@lam; y = tf32(xu*coef)
// xu rows are DIM-strided (written by gemm_tc epilogue).
// ---------------------------------------------------------------------------
__global__ __launch_bounds__(256) void route_scale(
    const float* __restrict__ Wg1, const float* __restrict__ Wg2,
    const float* __restrict__ lam, int k, int KP)
{
    int n = blockIdx.x;
    float* row = g_xu + (size_t)n * DIM;
    __shared__ float red[256];
    int tid = threadIdx.x;

    float p = 0.0f;
    for (int c = tid; c < k; c += 256) p += row[c] * Wg1[c];
    red[tid] = p;
    __syncthreads();
    #pragma unroll
    for (int s = 128; s > 0; s >>= 1) {
        if (tid < s) red[tid] += red[tid + s];
        __syncthreads();
    }
    float sv = red[0];

    float g[NE];
    float m = -1e30f;
    #pragma unroll
    for (int e = 0; e < NE; e++) { g[e] = sv * Wg2[e]; m = fmaxf(m, g[e]); }
    float sum = 0.0f;
    #pragma unroll
    for (int e = 0; e < NE; e++) { g[e] = expf(g[e] - m); sum += g[e]; }
    float inv = 1.0f / sum;
    #pragma unroll
    for (int e = 0; e < NE; e++) g[e] *= inv;

    for (int c = tid; c < KP; c += 256) {
        float coef = 0.0f;
        if (c < k) {
            #pragma unroll
            for (int e = 0; e < NE; e++) coef += g[e] * lam[(size_t)e * k + c];
        }
        row[c] = tf32r(row[c] * coef);
    }
}

// ---------------------------------------------------------------------------
// Launch  (order chosen so launch index 3 = gemm_xu for ncu capture)
// ---------------------------------------------------------------------------
extern "C" void kernel_launch(void* const* d_in, const int* in_sizes, int n_in,
                              void* d_out, int out_size)
{
    const float* x   = (const float*)d_in[0];  // [N, D]
    const float* W   = (const float*)d_in[1];  // [D, D]
    const float* Uk  = (const float*)d_in[2];  // [D, k]
    const float* Vk  = (const float*)d_in[3];  // [D, k]
    const float* lam = (const float*)d_in[4];  // [E, k]
    const float* v   = (const float*)d_in[5];  // [D]
    const float* Wg1 = (const float*)d_in[6];  // [k, 1]
    const float* Wg2 = (const float*)d_in[7];  // [1, E]
    float* out = (float*)d_out;

    int k = in_sizes[2] / DIM;
    if (k > KMAX) k = KMAX;
    int KP = ((k + 127) / 128) * 128;
    if (KP > KMAX) KP = KMAX;

    size_t smem_bytes = SMEM_FLTS * sizeof(float);  // 110592
    cudaFuncSetAttribute(gemm_tc, cudaFuncAttributeMaxDynamicSharedMemorySize, (int)smem_bytes);

    float* ukt; cudaGetSymbolAddress((void**)&ukt, g_ukt);
    float* vr;  cudaGetSymbolAddress((void**)&vr,  g_vr);
    float* xu;  cudaGetSymbolAddress((void**)&xu,  g_xu);
    float* wt;  cudaGetSymbolAddress((void**)&wt,  g_wt);

    // 1) B-operand prep (A operand = raw x, rounded by MMA HW truncation)
    trans_w<<<dim3(DIM / 32, DIM / 32), dim3(32, 8)>>>(W);
    trans_u<<<dim3(KP / 32, DIM / 32), dim3(32, 8)>>>(Uk, k);
    pad_v<<<4096, 256>>>(Vk, k, KP);

    // 2) xu = x @ U_k   (launch index 3 -> ncu capture slot)
    gemm_tc<<<dim3(KP / BN, N_TOK / BM), NTHR, smem_bytes>>>(
        x, ukt, DIM / BK, nullptr, nullptr, 0, xu, nullptr);

    // 3) routing + in-place y = tf32(xu * coef)
    route_scale<<<N_TOK, 256>>>(Wg1, Wg2, lam, k, KP);

    // 4) out = (x@W + y@V^T) * (1+v)   (fused K, tensor cores)
    gemm_tc<<<dim3(DIM / BN, N_TOK / BM), NTHR, smem_bytes>>>(
        x, wt, DIM / BK, xu, vr, KP / BK, out, v);
}